// round 2
// baseline (speedup 1.0000x reference)
#include <cuda_runtime.h>
#include <math.h>
#include <stddef.h>

// Problem dims
#define TT 512
#define BB 64
#define II 256
#define HH 512
#define OO 256
#define G4 (4*HH)          // 2048 gate columns
#define NBLK 128
#define WPAD (HH + 4)      // padded W row stride (floats) -> kills jj bank conflict

// ---------------- device scratch (no runtime allocation allowed) ----------------
__device__ float g_xp1[(size_t)TT*BB*G4];   // 256 MB
__device__ float g_xp2[(size_t)BB*G4];
__device__ float g_hA[(size_t)BB*HH];
__device__ float g_hB[(size_t)BB*HH];
__device__ float g_hs2[(size_t)TT*BB*HH];   // 64 MB
__device__ unsigned g_count = 0;
__device__ unsigned g_gen   = 0;

// =================================================================================
// Generic SGEMM: C[M,N] = A[M,K] * B[N,K]^T + bias1[N] (+ bias2[N])
// =================================================================================
__global__ __launch_bounds__(256) void gemm_bias_kernel(
    const float* __restrict__ A, const float* __restrict__ B,
    const float* __restrict__ bias1, const float* __restrict__ bias2,
    float* __restrict__ C, int M, int N, int K)
{
    __shared__ float As[8][128];
    __shared__ float Bs[8][128];

    const int tid  = threadIdx.x;
    const int row0 = blockIdx.y * 128;
    const int col0 = blockIdx.x * 128;

    const int lrow = tid >> 1;
    const int lcol = (tid & 1) << 2;
    const int tr   = (tid >> 4) << 3;
    const int tc   = (tid & 15) << 3;

    float acc[8][8];
    #pragma unroll
    for (int i = 0; i < 8; i++)
        #pragma unroll
        for (int j = 0; j < 8; j++) acc[i][j] = 0.f;

    for (int k0 = 0; k0 < K; k0 += 8) {
        float4 av = make_float4(0.f, 0.f, 0.f, 0.f);
        if (row0 + lrow < M)
            av = *(const float4*)(A + (size_t)(row0 + lrow) * K + k0 + lcol);
        As[lcol+0][lrow] = av.x;
        As[lcol+1][lrow] = av.y;
        As[lcol+2][lrow] = av.z;
        As[lcol+3][lrow] = av.w;

        float4 bv = *(const float4*)(B + (size_t)(col0 + lrow) * K + k0 + lcol);
        Bs[lcol+0][lrow] = bv.x;
        Bs[lcol+1][lrow] = bv.y;
        Bs[lcol+2][lrow] = bv.z;
        Bs[lcol+3][lrow] = bv.w;

        __syncthreads();

        #pragma unroll
        for (int kk = 0; kk < 8; kk++) {
            float ra[8], rb[8];
            *(float4*)(ra)     = *(const float4*)&As[kk][tr];
            *(float4*)(ra + 4) = *(const float4*)&As[kk][tr + 4];
            *(float4*)(rb)     = *(const float4*)&Bs[kk][tc];
            *(float4*)(rb + 4) = *(const float4*)&Bs[kk][tc + 4];
            #pragma unroll
            for (int i = 0; i < 8; i++)
                #pragma unroll
                for (int j = 0; j < 8; j++)
                    acc[i][j] += ra[i] * rb[j];
        }
        __syncthreads();
    }

    float bsum[8];
    #pragma unroll
    for (int j = 0; j < 8; j++) {
        float b = bias1 ? bias1[col0 + tc + j] : 0.f;
        if (bias2) b += bias2[col0 + tc + j];
        bsum[j] = b;
    }

    #pragma unroll
    for (int i = 0; i < 8; i++) {
        int r = row0 + tr + i;
        if (r < M) {
            #pragma unroll
            for (int j = 0; j < 8; j += 4) {
                float4 o;
                o.x = acc[i][j+0] + bsum[j+0];
                o.y = acc[i][j+1] + bsum[j+1];
                o.z = acc[i][j+2] + bsum[j+2];
                o.w = acc[i][j+3] + bsum[j+3];
                *(float4*)(C + (size_t)r * N + col0 + tc + j) = o;
            }
        }
    }
}

// =================================================================================
// Grid barrier (cooperative grid.sync pattern): bar.sync -> acq_rel arrive ->
// acquire spin -> bar.sync. Generation-counted, wrap-safe, persists across launches.
// =================================================================================
__device__ __forceinline__ unsigned atom_add_acqrel(unsigned* p, unsigned v) {
    unsigned r;
    asm volatile("atom.global.acq_rel.gpu.add.u32 %0, [%1], %2;"
                 : "=r"(r) : "l"(p), "r"(v) : "memory");
    return r;
}
__device__ __forceinline__ unsigned ld_acquire(unsigned* p) {
    unsigned r;
    asm volatile("ld.global.acquire.gpu.u32 %0, [%1];"
                 : "=r"(r) : "l"(p) : "memory");
    return r;
}

__device__ __forceinline__ void grid_barrier(unsigned target) {
    __syncthreads();
    if (threadIdx.x == 0) {
        if (atom_add_acqrel(&g_count, 1u) == NBLK - 1) {
            *(volatile unsigned*)&g_count = 0;      // ordered by release below
            atom_add_acqrel(&g_gen, 1u);
        } else {
            while (ld_acquire(&g_gen) != target) { __nanosleep(64); }
        }
    }
    __syncthreads();
}

// =================================================================================
// Persistent LSTM layer: 128 blocks x 256 threads, all 512 steps in one launch.
// Block owns JT=4 hidden columns (all 4 gates, all 64 batches). W staged once.
// c lives in registers of the 64 activation threads. h ping-pongs through gmem.
// =================================================================================
#define JT 4
#define STEP_SMEM_FLOATS (32768 + 16*WPAD + 256*16)   // hS + wS(padded) + red
#define STEP_SMEM_BYTES  (STEP_SMEM_FLOATS * 4)       // 180480 B

__device__ __forceinline__ float sigf(float x) { return 1.f / (1.f + expf(-x)); }

__global__ __launch_bounds__(256, 1) void lstm_persist_kernel(
    const float* __restrict__ h0, const float* __restrict__ c0,
    float* __restrict__ hA, float* __restrict__ hB,
    const float* __restrict__ W, const float* __restrict__ xp,
    long long xp_t_stride, float* __restrict__ hs_out)
{
    extern __shared__ float smem[];
    float4* hS  = (float4*)smem;                 // 8192 float4, swizzled h
    float*  wS  = smem + 32768;                  // 16 rows x WPAD
    float*  red = smem + 32768 + 16*WPAD;        // 256 x 16 partials

    const int tid = threadIdx.x;
    const int bg  = tid & 15;
    const int jj  = (tid >> 4) & 3;
    const int ks  = tid >> 6;
    const int jj0 = blockIdx.x * JT;

    // ---- stage W once (rows padded to WPAD floats) ----
    for (int idx = tid; idx < 16 * (HH/4); idx += 256) {
        int r  = idx >> 7;
        int c4 = idx & 127;
        int g  = r >> 2, j = r & 3;
        *(float4*)(wS + r * WPAD + c4 * 4) =
            ((const float4*)(W + (size_t)(g * HH + jj0 + j) * HH))[c4];
    }

    // ---- activation-thread state: c in registers for the whole sequence ----
    const int bg2 = tid & 15, jj2 = tid >> 4;    // valid when tid < 64
    const int jg  = jj0 + jj2;
    float creg[4];
    if (tid < 64) {
        #pragma unroll
        for (int i = 0; i < 4; i++)
            creg[i] = c0[(size_t)(bg2 * 4 + i) * HH + jg];
    }

    unsigned base_gen;
    {
        __shared__ unsigned s_gen;
        if (tid == 0) s_gen = ld_acquire(&g_gen);
        __syncthreads();
        base_gen = s_gen;
    }

    const int sw = bg & 7;
    const int b0 = bg << 2;
    const float4* w0 = (const float4*)(wS + (0*4 + jj) * WPAD);
    const float4* w1 = (const float4*)(wS + (1*4 + jj) * WPAD);
    const float4* w2 = (const float4*)(wS + (2*4 + jj) * WPAD);
    const float4* w3 = (const float4*)(wS + (3*4 + jj) * WPAD);
    const int k4beg = ks * 32;

    for (int t = 0; t < TT; t++) {
        const float* hsrc = (t == 0) ? h0 : ((t & 1) ? hB : hA);
        float*       hdst = (t & 1) ? hA : hB;

        // ---- stage h, swizzled ----
        for (int idx = tid; idx < BB * (HH/4); idx += 256) {
            int b = idx >> 7, k4 = idx & 127;
            hS[b * 128 + (k4 ^ ((b >> 2) & 7))] = ((const float4*)hsrc)[idx];
        }

        // ---- prefetch xp gate inputs (hide DRAM behind compute) ----
        float xi[4], xf[4], xg[4], xo[4];
        if (tid < 64) {
            const float* xt = xp + (size_t)(xp_t_stride * t);
            #pragma unroll
            for (int i = 0; i < 4; i++) {
                const float* xb = xt + (size_t)(bg2 * 4 + i) * G4;
                xi[i] = xb[0*HH + jg];
                xf[i] = xb[1*HH + jg];
                xg[i] = xb[2*HH + jg];
                xo[i] = xb[3*HH + jg];
            }
        }
        __syncthreads();

        // ---- dot products: 4 batches x 4 gates per thread, k-slice ks ----
        float acc[4][4];
        #pragma unroll
        for (int i = 0; i < 4; i++)
            #pragma unroll
            for (int g = 0; g < 4; g++) acc[i][g] = 0.f;

        #pragma unroll 4
        for (int k4 = k4beg; k4 < k4beg + 32; k4++) {
            float4 wv[4];
            wv[0] = w0[k4]; wv[1] = w1[k4]; wv[2] = w2[k4]; wv[3] = w3[k4];
            int kx = k4 ^ sw;
            #pragma unroll
            for (int i = 0; i < 4; i++) {
                float4 hv = hS[(b0 + i) * 128 + kx];
                #pragma unroll
                for (int g = 0; g < 4; g++) {
                    acc[i][g] += hv.x * wv[g].x;
                    acc[i][g] += hv.y * wv[g].y;
                    acc[i][g] += hv.z * wv[g].z;
                    acc[i][g] += hv.w * wv[g].w;
                }
            }
        }

        #pragma unroll
        for (int i = 0; i < 4; i++)
            ((float4*)red)[tid * 4 + i] =
                make_float4(acc[i][0], acc[i][1], acc[i][2], acc[i][3]);
        __syncthreads();

        // ---- reduce + activations + state update ----
        if (tid < 64) {
            #pragma unroll
            for (int i = 0; i < 4; i++) {
                int b = bg2 * 4 + i;
                float4 s = ((float4*)red)[(0 * 64 + tid) * 4 + i];
                #pragma unroll
                for (int k = 1; k < 4; k++) {
                    float4 p = ((float4*)red)[(k * 64 + tid) * 4 + i];
                    s.x += p.x; s.y += p.y; s.z += p.z; s.w += p.w;
                }
                float gi = sigf (s.x + xi[i]);
                float gf = sigf (s.y + xf[i]);
                float gg = tanhf(s.z + xg[i]);
                float go = sigf (s.w + xo[i]);
                float cn = gf * creg[i] + gi * gg;
                creg[i] = cn;
                float hn = go * tanhf(cn);
                hdst[(size_t)b * HH + jg] = hn;
                if (hs_out)
                    hs_out[(size_t)t * BB * HH + (size_t)b * HH + jg] = hn;
            }
            __threadfence();   // publish h (and hs) to gpu scope before arrive
        }

        if (t != TT - 1)
            grid_barrier(base_gen + (unsigned)t + 1u);
    }
}

// =================================================================================
// Host launch — 5 graph nodes total
// =================================================================================
extern "C" void kernel_launch(void* const* d_in, const int* in_sizes, int n_in,
                              void* d_out, int out_size)
{
    (void)in_sizes; (void)n_in; (void)out_size;
    const float* inputs = (const float*)d_in[0];
    const float* W_ih1  = (const float*)d_in[1];
    const float* W_hh1  = (const float*)d_in[2];
    const float* b_ih1  = (const float*)d_in[3];
    const float* b_hh1  = (const float*)d_in[4];
    const float* W_ih2  = (const float*)d_in[5];
    const float* W_hh2  = (const float*)d_in[6];
    const float* b_ih2  = (const float*)d_in[7];
    const float* b_hh2  = (const float*)d_in[8];
    const float* W_lin  = (const float*)d_in[9];
    const float* b_lin  = (const float*)d_in[10];
    const float* h1_0   = (const float*)d_in[11];
    const float* c1_0   = (const float*)d_in[12];
    const float* h2_0   = (const float*)d_in[13];
    const float* c2_0   = (const float*)d_in[14];
    float* out = (float*)d_out;

    float *xp1, *xp2, *hA, *hB, *hs2;
    cudaGetSymbolAddress((void**)&xp1, g_xp1);
    cudaGetSymbolAddress((void**)&xp2, g_xp2);
    cudaGetSymbolAddress((void**)&hA,  g_hA);
    cudaGetSymbolAddress((void**)&hB,  g_hB);
    cudaGetSymbolAddress((void**)&hs2, g_hs2);

    cudaFuncSetAttribute(lstm_persist_kernel,
                         cudaFuncAttributeMaxDynamicSharedMemorySize,
                         STEP_SMEM_BYTES);

    // xp1 = inputs @ W_ih1^T + b_ih1 + b_hh1   (M=32768, N=2048, K=256)
    gemm_bias_kernel<<<dim3(G4/128, (TT*BB)/128), 256>>>(
        inputs, W_ih1, b_ih1, b_hh1, xp1, TT*BB, G4, II);

    // Layer 1: persistent, 512 steps. Final h1T lands in hA (t=511 odd -> hA).
    lstm_persist_kernel<<<NBLK, 256, STEP_SMEM_BYTES>>>(
        h1_0, c1_0, hA, hB, W_hh1, xp1, (long long)BB * G4, nullptr);

    // xp2 = h1T @ W_ih2^T + b_ih2 + b_hh2   (M=64, N=2048, K=512)
    gemm_bias_kernel<<<dim3(G4/128, 1), 256>>>(
        hA, W_ih2, b_ih2, b_hh2, xp2, BB, G4, HH);

    // Layer 2: persistent, constant xp, hidden sequence streamed out.
    lstm_persist_kernel<<<NBLK, 256, STEP_SMEM_BYTES>>>(
        h2_0, c2_0, hA, hB, W_hh2, xp2, 0LL, hs2);

    // out = hs2 @ W_lin^T + b_lin   (M=32768, N=256, K=512)
    gemm_bias_kernel<<<dim3(OO/128, (TT*BB)/128), 256>>>(
        hs2, W_lin, b_lin, nullptr, out, TT*BB, OO, HH);
}